// round 7
// baseline (speedup 1.0000x reference)
#include <cuda_runtime.h>
#include <cstdint>
#include <cstddef>

#define N_TOK   131072
#define DIM     64
#define KCODES  1024
#define CHUNK   64          // codes per smem chunk (raw floats: 64*64*4 = 16KB)
#define NCHUNKS (KCODES / CHUNK)
#define QBLOCKS 512         // quantize kernel blocks (256 tokens each)

// Output layout (float32, flattened tuple order):
//   [0]                      loss
//   [1 .. 1+N*D)             quantized_st
//   [1+N*D]                  perplexity
//   [2+N*D .. 2+N*D+N)       encoding_indices (as float)
#define OUT_Q    ((size_t)1)
#define OUT_PERP ((size_t)1 + (size_t)N_TOK * DIM)
#define OUT_IDX  ((size_t)2 + (size_t)N_TOK * DIM)

typedef unsigned long long u64;

// ---------------- device scratch (no allocations allowed) ----------------
__device__ float  g_e2[KCODES];
__device__ int    g_idx[N_TOK];
__device__ int    g_counts[KCODES];
__device__ double g_block_sse[QBLOCKS];

// ---------------- packed f32x2 helpers (FFMA2 path, sm_103a) -------------
__device__ __forceinline__ void ffma2(u64& d, u64 a, u64 b) {
    asm("fma.rn.f32x2 %0, %1, %2, %0;" : "+l"(d) : "l"(a), "l"(b));
}
__device__ __forceinline__ float2 unpack2(u64 v) {
    float2 f; asm("mov.b64 {%0, %1}, %2;" : "=f"(f.x), "=f"(f.y) : "l"(v)); return f;
}

// ---------------- cp.async helpers ---------------------------------------
__device__ __forceinline__ void cp_async16(void* smem_dst, const void* gsrc) {
    uint32_t s = (uint32_t)__cvta_generic_to_shared(smem_dst);
    asm volatile("cp.async.cg.shared.global [%0], [%1], 16;" :: "r"(s), "l"(gsrc));
}
__device__ __forceinline__ void cp_commit() {
    asm volatile("cp.async.commit_group;");
}
template <int N>
__device__ __forceinline__ void cp_wait() {
    asm volatile("cp.async.wait_group %0;" :: "n"(N));
}

// ---------------- kernel 0: prep (e2 per code, zero counts) --------------
__global__ void vq_prep_kernel(const float* __restrict__ cb) {
    int k = blockIdx.x * blockDim.x + threadIdx.x;
    if (k < KCODES) {
        const float* row = cb + (size_t)k * DIM;
        float s0 = 0.f, s1 = 0.f, s2 = 0.f, s3 = 0.f;
        #pragma unroll
        for (int i = 0; i < DIM; i += 4) {
            s0 = fmaf(row[i+0], row[i+0], s0);
            s1 = fmaf(row[i+1], row[i+1], s1);
            s2 = fmaf(row[i+2], row[i+2], s2);
            s3 = fmaf(row[i+3], row[i+3], s3);
        }
        g_e2[k] = (s0 + s1) + (s2 + s3);
        g_counts[k] = 0;
    }
}

// ---------------- kernel 1: argmin (the hot GEMM-like kernel) ------------
// 256 threads/CTA, 2 CTAs/SM (4 warps/SMSP). ONE token per thread.
// ARITHMETIC IS FROZEN to the R4-passing order:
//   x2  : single packed chain over all dims, then lane.x + lane.y
//   dot : single packed chain a += px[2i]*v.x; a += px[2i+1]*v.y
//         (lane.x = even dims in order, lane.y = odd dims), then .x + .y
//   d   = fmaf(dot, -2, x2) + e2 ; strict '<' with ascending code index.
// Argmin ties sit at ulp level -> any reordering flips indices (R5 lesson).
__global__ void __launch_bounds__(256, 2)
vq_argmin_kernel(const float* __restrict__ x, const float* __restrict__ cb,
                 float* __restrict__ out_idx_f) {
    __shared__ __align__(16) float s_e[2][CHUNK * DIM];   // 2 x 16KB
    __shared__ float s_e2[KCODES];                        // 4KB

    const int tid = threadIdx.x;
    const int t   = blockIdx.x * 256 + tid;               // token index

    // e2 table -> smem (once)
    #pragma unroll
    for (int i = 0; i < KCODES / 256; ++i)
        s_e2[i * 256 + tid] = g_e2[i * 256 + tid];

    // Load token row; consecutive-dim pairs are native f32x2 operands.
    u64 px[DIM / 2];
    {
        const ulonglong2* r = reinterpret_cast<const ulonglong2*>(x + (size_t)t * DIM);
        #pragma unroll
        for (int i = 0; i < DIM / 4; ++i) {
            ulonglong2 v = r[i];
            px[2*i]   = v.x;
            px[2*i+1] = v.y;
        }
    }

    // |x|^2 : single chain over all packed pairs (R4 order)
    float x2;
    {
        u64 qa = 0ull;
        #pragma unroll
        for (int j = 0; j < DIM / 2; ++j)
            ffma2(qa, px[j], px[j]);
        float2 f = unpack2(qa);
        x2 = f.x + f.y;
    }

    // Prefetch chunk 0 (16KB = 1024 x 16B; 4 per thread)
    const float4* csrc = reinterpret_cast<const float4*>(cb);
    {
        float4* dst = reinterpret_cast<float4*>(s_e[0]);
        #pragma unroll
        for (int j = 0; j < 4; ++j)
            cp_async16(dst + j * 256 + tid, csrc + j * 256 + tid);
        cp_commit();
    }

    float best = 3.4e38f;
    int   bi   = 0;
    int   buf  = 0;

    for (int cc = 0; cc < NCHUNKS; ++cc) {
        const int c0 = cc * CHUNK;
        if (cc < NCHUNKS - 1) {
            const float4* src = csrc + (size_t)(c0 + CHUNK) * (DIM / 4);
            float4* dst = reinterpret_cast<float4*>(s_e[buf ^ 1]);
            #pragma unroll
            for (int j = 0; j < 4; ++j)
                cp_async16(dst + j * 256 + tid, src + j * 256 + tid);
            cp_commit();
            cp_wait<1>();       // chunk cc has landed; cc+1 still in flight
        } else {
            cp_wait<0>();
        }
        __syncthreads();

        const float* sb = s_e[buf];
        #pragma unroll 2
        for (int k = 0; k < CHUNK; ++k) {
            const ulonglong2* e = reinterpret_cast<const ulonglong2*>(sb + k * DIM);
            u64 a = 0ull;             // SINGLE chain (R4-exact rounding order)
            #pragma unroll
            for (int i = 0; i < DIM / 4; ++i) {
                ulonglong2 v = e[i];              // broadcast LDS.128
                ffma2(a, px[2*i],   v.x);
                ffma2(a, px[2*i+1], v.y);
            }
            float2 f = unpack2(a);
            float dot = f.x + f.y;
            float d = fmaf(dot, -2.0f, x2) + s_e2[c0 + k];
            if (d < best) { best = d; bi = c0 + k; }
        }
        __syncthreads();        // all warps done with s_e[buf] before overwrite
        buf ^= 1;
    }

    g_idx[t] = bi;
    out_idx_f[t] = (float)bi;
}

// ---------------- kernel 2: quantize + MSE partials + histogram ----------
// 512 CTAs x 256 threads; each CTA handles 256 tokens.
// Thread = (token sub-slot, dim): tid = sub*64 + dim -> coalesced I/O.
// NOTE: output region starts at dout+1 (4B offset) -> stores MUST be scalar.
__global__ void __launch_bounds__(256)
vq_quantize_kernel(const float* __restrict__ x, const float* __restrict__ cb,
                   float* __restrict__ dout) {
    __shared__ int   sbins[KCODES];
    __shared__ float swarp[8];

    for (int i = threadIdx.x; i < KCODES; i += 256) sbins[i] = 0;
    __syncthreads();

    const int dim  = threadIdx.x & 63;
    const int sub  = threadIdx.x >> 6;     // 0..3
    const int base = blockIdx.x * 256;

    float lsum = 0.f;
    #pragma unroll 4
    for (int it = 0; it < 64; ++it) {
        int t   = base + it * 4 + sub;
        int idx = g_idx[t];
        float q  = cb[(size_t)idx * DIM + dim];
        float xv = x[(size_t)t * DIM + dim];
        float df = q - xv;                              // quantized - inputs
        dout[OUT_Q + (size_t)t * DIM + dim] = xv + df;  // straight-through value
        lsum = fmaf(df, df, lsum);
        if (dim == 0) atomicAdd(&sbins[idx], 1);
    }

    // block-reduce lsum (deterministic tree)
    #pragma unroll
    for (int o = 16; o > 0; o >>= 1) lsum += __shfl_down_sync(0xffffffffu, lsum, o);
    if ((threadIdx.x & 31) == 0) swarp[threadIdx.x >> 5] = lsum;
    __syncthreads();
    if (threadIdx.x == 0) {
        float s = 0.f;
        #pragma unroll
        for (int w = 0; w < 8; ++w) s += swarp[w];
        g_block_sse[blockIdx.x] = (double)s;
    }

    // merge histogram (integer atomics: exact + deterministic)
    for (int i = threadIdx.x; i < KCODES; i += 256) {
        int c = sbins[i];
        if (c) atomicAdd(&g_counts[i], c);
    }
}

// ---------------- kernel 3: finalize loss + perplexity -------------------
__global__ void vq_finalize_kernel(float* __restrict__ dout) {
    __shared__ double sd[256];
    const int tid = threadIdx.x;

    // deterministic sum of per-block SSE
    double s = 0.0;
    for (int i = tid; i < QBLOCKS; i += 256) s += g_block_sse[i];
    sd[tid] = s;
    __syncthreads();
    #pragma unroll
    for (int o = 128; o > 0; o >>= 1) {
        if (tid < o) sd[tid] += sd[tid + o];
        __syncthreads();
    }
    double sse = sd[0];
    __syncthreads();

    // entropy: H = sum p*log(p + 1e-10), p = counts / N
    double h = 0.0;
    for (int i = tid; i < KCODES; i += 256) {
        float p = (float)g_counts[i] * (1.0f / (float)N_TOK);
        h += (double)(p * logf(p + 1e-10f));
    }
    sd[tid] = h;
    __syncthreads();
    #pragma unroll
    for (int o = 128; o > 0; o >>= 1) {
        if (tid < o) sd[tid] += sd[tid + o];
        __syncthreads();
    }

    if (tid == 0) {
        float mse = (float)(sse / ((double)N_TOK * (double)DIM));
        dout[0]        = mse + 0.25f * mse;          // (1 + beta) * mse
        dout[OUT_PERP] = expf((float)(-sd[0]));      // exp(-sum p log p)
    }
}

// ---------------- launch ---------------------------------------------------
extern "C" void kernel_launch(void* const* d_in, const int* in_sizes, int n_in,
                              void* d_out, int out_size) {
    const float* x  = (const float*)d_in[0];
    const float* cb = (const float*)d_in[1];
    // defensive: metadata order is (inputs, codebook); swap if sizes disagree
    if (n_in >= 2 && in_sizes[0] == KCODES * DIM && in_sizes[1] == N_TOK * DIM) {
        const float* t = x; x = cb; cb = t;
    }
    float* out = (float*)d_out;

    vq_prep_kernel<<<(KCODES + 255) / 256, 256>>>(cb);
    vq_argmin_kernel<<<N_TOK / 256, 256>>>(x, cb, out + OUT_IDX);
    vq_quantize_kernel<<<QBLOCKS, 256>>>(x, cb, out);
    vq_finalize_kernel<<<1, 256>>>(out);
}